// round 14
// baseline (speedup 1.0000x reference)
#include <cuda_runtime.h>
#include <cstdint>
#include <math.h>

#define DB 32
#define DT 2048
#define DI 128
#define DH 256
#define NBC 4   // batches per cluster (interleaved in the scan)

// Scratch (allocation-free rule: __device__ globals), 256B-aligned for LDG/STG.128.
__device__ __align__(256) float g_xb[DB * DT * DH];
__device__ __align__(256) float g_hs[DB * DT * DH];

// ---------------- PTX helpers ----------------
__device__ __forceinline__ uint32_t smem_u32(const void* p) {
    return (uint32_t)__cvta_generic_to_shared(p);
}
__device__ __forceinline__ uint32_t mapa_u32(uint32_t a, uint32_t rank) {
    uint32_t r;
    asm volatile("mapa.shared::cluster.u32 %0, %1, %2;" : "=r"(r) : "r"(a), "r"(rank));
    return r;
}
__device__ __forceinline__ void mbar_init(uint32_t a, uint32_t cnt) {
    asm volatile("mbarrier.init.shared.b64 [%0], %1;" :: "r"(a), "r"(cnt) : "memory");
}
__device__ __forceinline__ void mbar_arrive_cluster(uint32_t a) {
    asm volatile("mbarrier.arrive.release.cluster.shared::cluster.b64 _, [%0];"
                 :: "r"(a) : "memory");
}
__device__ __forceinline__ void st_cluster_v4(uint32_t a, float4 v) {
    asm volatile("st.shared::cluster.v4.f32 [%0], {%1, %2, %3, %4};"
                 :: "r"(a), "f"(v.x), "f"(v.y), "f"(v.z), "f"(v.w) : "memory");
}
// CTA-scope acquire wait with suspend hint: peers' release.cluster arrives land
// AFTER their data stores into OUR smem, so cta-scope acquire suffices.
__device__ __forceinline__ void mbar_wait_parity_cta(uint32_t a, uint32_t parity) {
    asm volatile(
        "{\n\t"
        ".reg .pred P;\n\t"
        "LWAIT_%=:\n\t"
        "mbarrier.try_wait.parity.acquire.cta.shared::cta.b64 P, [%0], %1, 0x989680;\n\t"
        "@!P bra LWAIT_%=;\n\t"
        "}" :: "r"(a), "r"(parity) : "memory");
}
__device__ __forceinline__ void cluster_arrive() {
    asm volatile("barrier.cluster.arrive.aligned;" ::: "memory");
}
__device__ __forceinline__ void cluster_wait() {
    asm volatile("barrier.cluster.wait.aligned;" ::: "memory");
}

// ---- packed f32x2 (scan dot only; R8 showed it hurts GEMM codegen) ----
__device__ __forceinline__ unsigned long long ffma2(unsigned long long a,
                                                    unsigned long long b,
                                                    unsigned long long c) {
    unsigned long long d;
    asm("fma.rn.f32x2 %0, %1, %2, %3;" : "=l"(d) : "l"(a), "l"(b), "l"(c));
    return d;
}
__device__ __forceinline__ unsigned long long pack2(float lo, float hi) {
    unsigned long long d;
    asm("mov.b64 %0, {%1, %2};" : "=l"(d) : "f"(lo), "f"(hi));
    return d;
}
__device__ __forceinline__ float2 unpack2(unsigned long long v) {
    float2 r;
    asm("mov.b64 {%0, %1}, %2;" : "=f"(r.x), "=f"(r.y) : "l"(v));
    return r;
}
__device__ __forceinline__ float tanh_fast(float x) {
    float r;
    asm("tanh.approx.f32 %0, %1;" : "=f"(r) : "f"(x));
    return r;
}

// ---------------- Tiled fp32 GEMM (R7/R12 version, measured 131us for xb) ------
template<int K_TOTAL>
__device__ __forceinline__ void gemm_body(const float* __restrict__ in,
                                          const float* __restrict__ W,
                                          float* __restrict__ out, int N)
{
    __shared__ __align__(16) float sA[64][68];  // transposed: sA[k][m]
    __shared__ __align__(16) float sB[64][64];  // sB[k][n]

    const int tx = threadIdx.x & 15;
    const int ty = threadIdx.x >> 4;
    const int mBase = blockIdx.y * 64;
    const int nBase = blockIdx.x * 64;

    float acc[4][4] = {};

    for (int k0 = 0; k0 < K_TOTAL; k0 += 64) {
        #pragma unroll
        for (int it = 0; it < 4; ++it) {
            int idx = threadIdx.x + it * 256;
            int m  = idx >> 4;
            int kq = idx & 15;
            float4 v = *(const float4*)(in + (size_t)(mBase + m) * K_TOTAL + k0 + kq * 4);
            sA[kq * 4 + 0][m] = v.x;
            sA[kq * 4 + 1][m] = v.y;
            sA[kq * 4 + 2][m] = v.z;
            sA[kq * 4 + 3][m] = v.w;
        }
        #pragma unroll
        for (int it = 0; it < 4; ++it) {
            int idx = threadIdx.x + it * 256;
            int k  = idx >> 4;
            int nq = idx & 15;
            *(float4*)(&sB[k][nq * 4]) =
                *(const float4*)(W + (size_t)(k0 + k) * N + nBase + nq * 4);
        }
        __syncthreads();

        #pragma unroll 8
        for (int k = 0; k < 64; ++k) {
            float4 a4 = *(const float4*)(&sA[k][ty * 4]);
            float4 b4 = *(const float4*)(&sB[k][tx * 4]);
            float av[4] = {a4.x, a4.y, a4.z, a4.w};
            float bv[4] = {b4.x, b4.y, b4.z, b4.w};
            #pragma unroll
            for (int i = 0; i < 4; ++i)
                #pragma unroll
                for (int jj = 0; jj < 4; ++jj)
                    acc[i][jj] = fmaf(av[i], bv[jj], acc[i][jj]);
        }
        __syncthreads();
    }

    #pragma unroll
    for (int i = 0; i < 4; ++i) {
        float4 v = make_float4(acc[i][0], acc[i][1], acc[i][2], acc[i][3]);
        *(float4*)(out + (size_t)(mBase + ty * 4 + i) * N + nBase + tx * 4) = v;
    }
}

__global__ void __launch_bounds__(256, 2)
gemm_xb_kernel(const float* __restrict__ x, const float* __restrict__ Bm)
{
    gemm_body<DI>(x, Bm, g_xb, DH);          // [B*T,128] @ [128,256] -> g_xb
}

__global__ void __launch_bounds__(256, 2)
gemm_out_kernel(const float* __restrict__ C, float* __restrict__ out)
{
    gemm_body<DH>(g_hs, C, out, DH);         // [B*T,256] @ [256,256] -> out
}

// ---------------- Scan: 4-CTA cluster, 4 batches interleaved per cluster ------
// 8 clusters x 4 CTAs = 32 CTAs. CTA rank r owns columns [64r,64r+64) of ALL
// 4 batches (A-regs shared). Per step t, batches are time-sliced:
//   for b: wait full[b][s] -> dot(b) -> __syncthreads -> producers: reduce(b)
//          + tanh + stage + STG hs; bar.sync(1,64); relay threads of batch b
//          (tid in [16b,16b+16)) push stage[b] to their dest CTA.
// While batch b's exchange is in flight, batches b+1..b+3 compute => the
// ~L-cycle DSMEM round trip is hidden behind ~3C of other-batch compute.
// Relay consolidation: 16 relays per batch per CTA; relay r: dest=r&3,
// quarter q=r>>2, stores 4x st.v4 (16 floats) + ONE arrive.
// full[b][slot] count = 16 (4 relays x 4 source CTAs). No empty barriers:
// 2-slot transitive backpressure as proven in R12. Terminal quiesce.
__global__ void __launch_bounds__(512, 1) __cluster_dims__(4, 1, 1)
scan_kernel(const float* __restrict__ A)
{
    __shared__ __align__(16) float h_buf[NBC][2][DH];    // 8 KB
    __shared__ __align__(16) float part[NBC][8][64];     // 8 KB
    __shared__ __align__(16) float stage[NBC][64];       // 1 KB
    __shared__ __align__(8)  unsigned long long mbars[NBC * 2];

    const int tid = threadIdx.x;
    const int j   = tid & 63;
    const int kc  = tid >> 6;                 // 0..7
    uint32_t rank;
    asm("mov.u32 %0, %%cluster_ctarank;" : "=r"(rank));
    const int cl   = blockIdx.x >> 2;         // cluster id 0..7
    const int colg = (int)rank * 64 + j;

    const uint32_t mb   = smem_u32(mbars);
    const uint32_t hb0  = smem_u32(&h_buf[0][0][0]);

    if (tid == 0) {
        #pragma unroll
        for (int i = 0; i < NBC * 2; ++i) mbar_init(mb + i * 8, 16);
    }
    #pragma unroll
    for (int b = 0; b < NBC; ++b)
        for (int i = tid; i < DH; i += 512) h_buf[b][0][i] = 0.f;  // h_0 = 0

    // A slice in registers: a2[q] = (A[kc*32+2q][colg], A[kc*32+2q+1][colg])
    unsigned long long a2[16];
    #pragma unroll
    for (int q = 0; q < 16; ++q)
        a2[q] = pack2(A[(size_t)(kc * 32 + 2 * q)     * DH + colg],
                      A[(size_t)(kc * 32 + 2 * q + 1) * DH + colg]);

    // Per-batch xb/hs pointers + depth-2 xb prefetch (producers only)
    const float* xb_b[NBC];
    float*       hs_b[NBC];
    float        xb_buf[NBC][2];
    #pragma unroll
    for (int b = 0; b < NBC; ++b) {
        const int batch = cl * NBC + b;
        xb_b[b] = g_xb + (size_t)batch * DT * DH + colg;
        hs_b[b] = g_hs + (size_t)batch * DT * DH + colg;
        xb_buf[b][0] = 0.f; xb_buf[b][1] = 0.f;
        if (tid < 64) {
            xb_buf[b][0] = __ldg(&xb_b[b][0]);
            xb_buf[b][1] = __ldg(&xb_b[b][(size_t)DH]);
        }
    }

    // Relay role (producers only): this thread relays batch rb = tid>>4,
    // relay slot r = tid&15: dest CTA = r&3, quarter q = r>>2.
    const int      rb     = (tid & 63) >> 4;
    const uint32_t dest_c = (uint32_t)(tid & 3);
    const int      q4     = (tid >> 2) & 3;

    __syncthreads();
    cluster_arrive(); cluster_wait();   // mbarriers + zeroed slot 0 visible

    unsigned pf[NBC][2] = {};

    for (int t = 0; t < DT; ++t) {
        const int s = t & 1;
        const int w = s ^ 1;

        #pragma unroll
        for (int b = 0; b < NBC; ++b) {
            const uint32_t full_s = mb + (b * 2 + s) * 8;
            const uint32_t full_w = mb + (b * 2 + w) * 8;

            if (t > 0) { mbar_wait_parity_cta(full_s, pf[b][s]); pf[b][s] ^= 1; }

            // Partial dot over this thread's 32-k chunk (warp-uniform LDS)
            {
                const ulonglong2* hb2 = (const ulonglong2*)(&h_buf[b][s][kc * 32]);
                unsigned long long acca = 0ull, accb = 0ull;
                #pragma unroll
                for (int i = 0; i < 8; ++i) {
                    ulonglong2 hv = hb2[i];
                    acca = ffma2(hv.x, a2[2 * i],     acca);
                    accb = ffma2(hv.y, a2[2 * i + 1], accb);
                }
                float2 pa = unpack2(acca), pb = unpack2(accb);
                part[b][kc][j] = (pa.x + pa.y) + (pb.x + pb.y);
            }
            __syncthreads();     // partials visible; h_buf[b][s] reads complete

            if (tid < 64) {
                float z = part[b][0][j] + part[b][1][j] + part[b][2][j] + part[b][3][j]
                        + part[b][4][j] + part[b][5][j] + part[b][6][j] + part[b][7][j]
                        + xb_buf[b][s];
                float hn = tanh_fast(z);
                stage[b][j] = hn;
                hs_b[b][(size_t)t * DH] = hn;          // fire-and-forget for phase 3
                if (t + 2 < DT) xb_buf[b][s] = __ldg(&xb_b[b][(size_t)(t + 2) * DH]);

                asm volatile("bar.sync 1, 64;" ::: "memory");   // stage[b] complete

                if (t + 1 < DT && rb == b) {
                    // Relay: 4x st.v4 (quarter q4 of stage[b]) + 1 arrive
                    const uint32_t dst_base = mapa_u32(
                        hb0 + (uint32_t)(((b * 2 + w) * DH) + (int)rank * 64 + q4 * 16) * 4,
                        dest_c);
                    #pragma unroll
                    for (int k = 0; k < 4; ++k) {
                        float4 v = *(const float4*)(&stage[b][q4 * 16 + k * 4]);
                        st_cluster_v4(dst_base + (uint32_t)k * 16, v);
                    }
                    mbar_arrive_cluster(mapa_u32(full_w, dest_c));
                }
            }
        }
    }

    // Quiesce before exit (remote arrives targeting us may still be in flight).
    cluster_arrive(); cluster_wait();
}

// ---------------- Launch ----------------
extern "C" void kernel_launch(void* const* d_in, const int* in_sizes, int n_in,
                              void* d_out, int out_size)
{
    const float* x  = (const float*)d_in[0];   // [32,2048,128]
    const float* A  = (const float*)d_in[1];   // [256,256]
    const float* Bm = (const float*)d_in[2];   // [128,256]
    const float* C  = (const float*)d_in[3];   // [256,256]
    float* out = (float*)d_out;                // [32,2048,256]

    // Phase 1: xb = x @ Bm
    {
        dim3 grid(DH / 64, (DB * DT) / 64);    // (4, 1024)
        gemm_xb_kernel<<<grid, 256>>>(x, Bm);
    }
    // Phase 2: scan — 8 clusters x 4 CTAs, 4 interleaved batches per cluster
    {
        scan_kernel<<<(DB / NBC) * 4, 512>>>(A);
    }
    // Phase 3: out = hs @ C
    {
        dim3 grid(DH / 64, (DB * DT) / 64);
        gemm_out_kernel<<<grid, 256>>>(C, out);
    }
}